// round 1
// baseline (speedup 1.0000x reference)
#include <cuda_runtime.h>
#include <cstdint>
#include <cstddef>

// Problem constants (fixed shapes from reference):
//   x:   (B=32, D=256, H=32, W=32) fp32
//   emb: (D=256, K=2048) fp32
//   out: (32, 256, 32, 32) fp32 = nearest code per latent
#define DDIM     256
#define KCODES   2048
#define SPATIAL  1024        // H*W per batch
#define BM       128         // latent rows per block tile
#define BKT      128         // codes per k-tile
#define DCH      16          // d-depth per smem chunk
#define NTHREADS 256
#define NCHUNKS  ((KCODES / BKT) * (DDIM / DCH))   // 256

// Scratch: 0.5*||e_k||^2 per code (device global: no allocs allowed).
__device__ float g_cnorm[KCODES];

// ---------------------------------------------------------------------------
// Kernel 1: cnorm[k] = 0.5 * sum_d emb[d][k]^2   (ascending-d fp32, like ref)
// ---------------------------------------------------------------------------
__global__ void cnorm_kernel(const float* __restrict__ emb) {
    int k = blockIdx.x * blockDim.x + threadIdx.x;
    float s = 0.0f;
#pragma unroll 8
    for (int d = 0; d < DDIM; ++d) {
        float e = emb[d * KCODES + k];
        s = fmaf(e, e, s);
    }
    g_cnorm[k] = 0.5f * s;
}

// ---------------------------------------------------------------------------
// Packed fp32x2 helpers (Blackwell sm_100+: fma.rn.f32x2 — PTX-only path)
// ---------------------------------------------------------------------------
__device__ __forceinline__ unsigned long long pack_dup(float x) {
    unsigned long long r;
    asm("mov.b64 %0, {%1, %2};" : "=l"(r) : "f"(x), "f"(x));
    return r;
}
__device__ __forceinline__ void unpack2(unsigned long long v, float& lo, float& hi) {
    asm("mov.b64 {%0, %1}, %2;" : "=f"(lo), "=f"(hi) : "l"(v));
}
__device__ __forceinline__ void fma2(unsigned long long& d,
                                     unsigned long long a,
                                     unsigned long long b) {
    asm("fma.rn.f32x2 %0, %1, %2, %0;" : "+l"(d) : "l"(a), "l"(b));
}
// Load an adjacent pair of fp32 from smem directly as one packed b64 register.
__device__ __forceinline__ unsigned long long lds_b64(const float* p) {
    unsigned long long r;
    unsigned sa = (unsigned)__cvta_generic_to_shared((const void*)p);
    asm volatile("ld.shared.b64 %0, [%1];" : "=l"(r) : "r"(sa));
    return r;
}

// ---------------------------------------------------------------------------
// Kernel 2: fused distance-GEMM + argmin + code gather.
// Grid: 256 blocks (N/BM). Block: 256 threads (16x16), 8x8 microtile.
// smem: 2 buffers x (Xs[16][128] + Es[16][128]) = 32 KB.
// ---------------------------------------------------------------------------
__global__ void __launch_bounds__(NTHREADS, 2)
nearest_main(const float* __restrict__ x, const float* __restrict__ emb,
             float* __restrict__ out) {
    __shared__ __align__(16) float smem[8192];

    const int t   = threadIdx.x;
    const int tx  = t & 15;        // column-group (codes)
    const int ty  = t >> 4;        // row-group (latents)
    const int bid = blockIdx.x;
    const int b   = bid >> 3;              // batch
    const int s0  = (bid & 7) * BM;        // spatial offset within batch
    const float* xb = x + (size_t)b * (DDIM * SPATIAL) + s0;

    // Loader mapping: each thread moves 2 float4 per operand per chunk.
    const int dd0 = t >> 5;            // 0..7
    const int i0  = (t & 31) * 4;      // 0..124
    const int dd1 = dd0 + 8;           // 8..15

    float4 px0, px1, pe0, pe1;

    // Prefetch chunk 0 (kt=0, dc=0).
    px0 = *(const float4*)(xb + dd0 * SPATIAL + i0);
    px1 = *(const float4*)(xb + dd1 * SPATIAL + i0);
    pe0 = *(const float4*)(emb + dd0 * KCODES + i0);
    pe1 = *(const float4*)(emb + dd1 * KCODES + i0);

    float best[8];
    int   bestk[8];
#pragma unroll
    for (int r = 0; r < 8; ++r) { best[r] = 3.4e38f; bestk[r] = 0; }

    for (int kt = 0; kt < KCODES / BKT; ++kt) {
        unsigned long long acc[8][4];
#pragma unroll
        for (int r = 0; r < 8; ++r)
#pragma unroll
            for (int j = 0; j < 4; ++j) acc[r][j] = 0ull;

        for (int dc = 0; dc < DDIM / DCH; ++dc) {
            const int c = (kt << 4) + dc;
            float* Xb = smem + (c & 1) * 4096;
            float* Eb = Xb + 2048;

            // Stage prefetched chunk c into smem.
            *(float4*)(Xb + dd0 * BM + i0)  = px0;
            *(float4*)(Xb + dd1 * BM + i0)  = px1;
            *(float4*)(Eb + dd0 * BKT + i0) = pe0;
            *(float4*)(Eb + dd1 * BKT + i0) = pe1;
            __syncthreads();

            // Prefetch chunk c+1 into registers (overlaps with compute below).
            if (c + 1 < NCHUNKS) {
                const int cn    = c + 1;
                const int ktn   = cn >> 4;
                const int dbase = (cn & 15) * DCH;
                px0 = *(const float4*)(xb + (dbase + dd0) * SPATIAL + i0);
                px1 = *(const float4*)(xb + (dbase + dd1) * SPATIAL + i0);
                const float* eb = emb + ktn * BKT;
                pe0 = *(const float4*)(eb + (dbase + dd0) * KCODES + i0);
                pe1 = *(const float4*)(eb + (dbase + dd1) * KCODES + i0);
            }

            const float* Xrow = Xb + ty * 8;
            const float* Erow = Eb + tx * 8;
#pragma unroll
            for (int dd = 0; dd < DCH; ++dd) {
                float4 a0 = *(const float4*)(Xrow + dd * BM);
                float4 a1 = *(const float4*)(Xrow + dd * BM + 4);
                unsigned long long b2[4];
                b2[0] = lds_b64(Erow + dd * BKT + 0);
                b2[1] = lds_b64(Erow + dd * BKT + 2);
                b2[2] = lds_b64(Erow + dd * BKT + 4);
                b2[3] = lds_b64(Erow + dd * BKT + 6);
                float av[8] = {a0.x, a0.y, a0.z, a0.w, a1.x, a1.y, a1.z, a1.w};
#pragma unroll
                for (int r = 0; r < 8; ++r) {
                    unsigned long long a2 = pack_dup(av[r]);
#pragma unroll
                    for (int j = 0; j < 4; ++j) fma2(acc[r][j], a2, b2[j]);
                }
            }
        }

        // k-tile epilogue: v = 0.5*||e||^2 - x.e ; running min (ascending k,
        // strict '<' keeps the earliest k on exact ties, matching argmin).
        const int kbase = kt * BKT + tx * 8;
        float cv[8];
#pragma unroll
        for (int j = 0; j < 8; ++j) cv[j] = __ldg(&g_cnorm[kbase + j]);
#pragma unroll
        for (int r = 0; r < 8; ++r) {
#pragma unroll
            for (int j = 0; j < 4; ++j) {
                float d0, d1;
                unpack2(acc[r][j], d0, d1);
                float v0 = cv[2 * j]     - d0;
                float v1 = cv[2 * j + 1] - d1;
                if (v0 < best[r]) { best[r] = v0; bestk[r] = kbase + 2 * j; }
                if (v1 < best[r]) { best[r] = v1; bestk[r] = kbase + 2 * j + 1; }
            }
        }
    }

    // Cross-thread reduction: 16 tx-threads share each row. Reuse tile smem.
    __syncthreads();
    float* rv = smem;                    // [16][128]
    int*   ri = (int*)(smem + 2048);     // [16][128]
    int*   km = (int*)(smem + 4096);     // [128]
#pragma unroll
    for (int r = 0; r < 8; ++r) {
        rv[tx * BM + ty * 8 + r] = best[r];
        ri[tx * BM + ty * 8 + r] = bestk[r];
    }
    __syncthreads();
    if (t < BM) {
        float bv = rv[t];
        int   bk = ri[t];
#pragma unroll
        for (int i = 1; i < 16; ++i) {
            float v  = rv[i * BM + t];
            int   kk = ri[i * BM + t];
            if (v < bv || (v == bv && kk < bk)) { bv = v; bk = kk; }
        }
        km[t] = bk;
    }
    __syncthreads();

    // Gather winning codes: out[b, d, s0+r] = emb[d, km[r]].
    // Consecutive threads -> consecutive r -> fully coalesced stores.
    float* ob = out + (size_t)b * (DDIM * SPATIAL) + s0;
    for (int idx = t; idx < BM * DDIM; idx += NTHREADS) {
        const int r = idx & (BM - 1);
        const int d = idx >> 7;
        ob[d * SPATIAL + r] = __ldg(&emb[d * KCODES + km[r]]);
    }
}

// ---------------------------------------------------------------------------
extern "C" void kernel_launch(void* const* d_in, const int* in_sizes, int n_in,
                              void* d_out, int out_size) {
    const float* x   = (const float*)d_in[0];
    const float* emb = (const float*)d_in[1];
    // Defensive: x (8.4M elems) is larger than emb (0.5M elems).
    if (n_in >= 2 && in_sizes[0] < in_sizes[1]) {
        emb = (const float*)d_in[0];
        x   = (const float*)d_in[1];
    }
    float* out = (float*)d_out;

    cnorm_kernel<<<KCODES / 256, 256>>>(emb);
    nearest_main<<<(32 * SPATIAL) / BM, NTHREADS>>>(x, emb, out);
}

// round 2
// speedup vs baseline: 1.1657x; 1.1657x over previous
#include <cuda_runtime.h>
#include <cstdint>
#include <cstddef>

// Problem constants (fixed shapes from reference):
//   x:   (B=32, D=256, H=32, W=32) fp32
//   emb: (D=256, K=2048) fp32
//   out: (32, 256, 32, 32) fp32 = nearest code per latent
#define DDIM     256
#define KCODES   2048
#define SPATIAL  1024        // H*W per batch
#define BM       128         // latent rows per block tile
#define BKT      128         // codes per k-tile
#define DCH      16          // d-depth per smem chunk
#define NTHREADS 256
#define NCHUNKS  ((KCODES / BKT) * (DDIM / DCH))   // 256

// Scratch: 0.5*||e_k||^2 per code (device global: no allocs allowed).
__device__ float g_cnorm[KCODES];

// ---------------------------------------------------------------------------
// Kernel 1: cnorm[k] = 0.5 * sum_d emb[d][k]^2   (ascending-d fp32, like ref)
// ---------------------------------------------------------------------------
__global__ void cnorm_kernel(const float* __restrict__ emb) {
    int k = blockIdx.x * blockDim.x + threadIdx.x;
    float s = 0.0f;
#pragma unroll 8
    for (int d = 0; d < DDIM; ++d) {
        float e = emb[d * KCODES + k];
        s = fmaf(e, e, s);
    }
    g_cnorm[k] = 0.5f * s;
}

// ---------------------------------------------------------------------------
// Packed fp32x2 helpers (Blackwell sm_100+: fma.rn.f32x2 — PTX-only path)
// ---------------------------------------------------------------------------
__device__ __forceinline__ unsigned long long pack_dup(float x) {
    unsigned long long r;
    asm("mov.b64 %0, {%1, %2};" : "=l"(r) : "f"(x), "f"(x));
    return r;
}
__device__ __forceinline__ void unpack2(unsigned long long v, float& lo, float& hi) {
    asm("mov.b64 {%0, %1}, %2;" : "=f"(lo), "=f"(hi) : "l"(v));
}
__device__ __forceinline__ void fma2(unsigned long long& d,
                                     unsigned long long a,
                                     unsigned long long b) {
    asm("fma.rn.f32x2 %0, %1, %2, %0;" : "+l"(d) : "l"(a), "l"(b));
}
// Load an adjacent pair of fp32 from smem directly as one packed b64 register.
__device__ __forceinline__ unsigned long long lds_b64(const float* p) {
    unsigned long long r;
    unsigned sa = (unsigned)__cvta_generic_to_shared((const void*)p);
    asm volatile("ld.shared.b64 %0, [%1];" : "=l"(r) : "r"(sa));
    return r;
}

// ---------------------------------------------------------------------------
// Kernel 2: fused distance-GEMM + argmin + code gather.
// Grid: 256 blocks (N/BM). Block: 256 threads (16x16), 8x8 microtile.
// Code mapping per thread: k = kt*128 + tx*2 + 32*j + {0,1}, j=0..3
//   -> E LDS.64 phase addresses stride 8B across tx: CONFLICT-FREE.
// Row mapping per thread:  r = ty*8 .. ty*8+7 (lanes 0-15 share ty: broadcast).
// smem: 2 buffers x (Xs[16][128] + Es[16][128]) = 32 KB.
// ---------------------------------------------------------------------------
__global__ void __launch_bounds__(NTHREADS, 2)
nearest_main(const float* __restrict__ x, const float* __restrict__ emb,
             float* __restrict__ out) {
    __shared__ __align__(16) float smem[8192];

    const int t   = threadIdx.x;
    const int tx  = t & 15;        // column-group (codes)
    const int ty  = t >> 4;        // row-group (latents)
    const int bid = blockIdx.x;
    const int b   = bid >> 3;              // batch
    const int s0  = (bid & 7) * BM;        // spatial offset within batch
    const float* xb = x + (size_t)b * (DDIM * SPATIAL) + s0;

    // Loader mapping: each thread moves 2 float4 per operand per chunk.
    const int dd0 = t >> 5;            // 0..7
    const int i0  = (t & 31) * 4;      // 0..124
    const int dd1 = dd0 + 8;           // 8..15

    float4 px0, px1, pe0, pe1;

    // Prefetch chunk 0 (kt=0, dc=0).
    px0 = *(const float4*)(xb + dd0 * SPATIAL + i0);
    px1 = *(const float4*)(xb + dd1 * SPATIAL + i0);
    pe0 = *(const float4*)(emb + dd0 * KCODES + i0);
    pe1 = *(const float4*)(emb + dd1 * KCODES + i0);

    float best[8];
    int   bestk[8];
#pragma unroll
    for (int r = 0; r < 8; ++r) { best[r] = 3.4e38f; bestk[r] = 0; }

    for (int kt = 0; kt < KCODES / BKT; ++kt) {
        unsigned long long acc[8][4];
#pragma unroll
        for (int r = 0; r < 8; ++r)
#pragma unroll
            for (int j = 0; j < 4; ++j) acc[r][j] = 0ull;

        for (int dc = 0; dc < DDIM / DCH; ++dc) {
            const int c = (kt << 4) + dc;
            float* Xb = smem + (c & 1) * 4096;
            float* Eb = Xb + 2048;

            // Stage prefetched chunk c into smem.
            *(float4*)(Xb + dd0 * BM + i0)  = px0;
            *(float4*)(Xb + dd1 * BM + i0)  = px1;
            *(float4*)(Eb + dd0 * BKT + i0) = pe0;
            *(float4*)(Eb + dd1 * BKT + i0) = pe1;
            __syncthreads();

            // Prefetch chunk c+1 into registers (overlaps with compute below).
            if (c + 1 < NCHUNKS) {
                const int cn    = c + 1;
                const int ktn   = cn >> 4;
                const int dbase = (cn & 15) * DCH;
                px0 = *(const float4*)(xb + (dbase + dd0) * SPATIAL + i0);
                px1 = *(const float4*)(xb + (dbase + dd1) * SPATIAL + i0);
                const float* eb = emb + ktn * BKT;
                pe0 = *(const float4*)(eb + (dbase + dd0) * KCODES + i0);
                pe1 = *(const float4*)(eb + (dbase + dd1) * KCODES + i0);
            }

            const float* Xrow = Xb + ty * 8;
            const float* Erow = Eb + tx * 2;   // stride-2: conflict-free b64
#pragma unroll
            for (int dd = 0; dd < DCH; ++dd) {
                float4 a0 = *(const float4*)(Xrow + dd * BM);
                float4 a1 = *(const float4*)(Xrow + dd * BM + 4);
                unsigned long long b2[4];
                b2[0] = lds_b64(Erow + dd * BKT + 0);
                b2[1] = lds_b64(Erow + dd * BKT + 32);
                b2[2] = lds_b64(Erow + dd * BKT + 64);
                b2[3] = lds_b64(Erow + dd * BKT + 96);
                float av[8] = {a0.x, a0.y, a0.z, a0.w, a1.x, a1.y, a1.z, a1.w};
#pragma unroll
                for (int r = 0; r < 8; ++r) {
                    unsigned long long a2 = pack_dup(av[r]);
#pragma unroll
                    for (int j = 0; j < 4; ++j) fma2(acc[r][j], a2, b2[j]);
                }
            }
        }

        // k-tile epilogue: v = 0.5*||e||^2 - x.e ; running min.
        // Thread's codes: kj = kt*128 + tx*2 + 32*j + {0,1}. Within a pair,
        // lo is the smaller k and j ascends in k, so strict '<' keeps the
        // earliest k inside this thread; cross-thread ties break in the
        // reduction below.
        const int kbase = kt * BKT + tx * 2;
        float cv[8];
#pragma unroll
        for (int j = 0; j < 4; ++j) {
            cv[2 * j]     = __ldg(&g_cnorm[kbase + 32 * j]);
            cv[2 * j + 1] = __ldg(&g_cnorm[kbase + 32 * j + 1]);
        }
#pragma unroll
        for (int r = 0; r < 8; ++r) {
#pragma unroll
            for (int j = 0; j < 4; ++j) {
                float d0, d1;
                unpack2(acc[r][j], d0, d1);
                float v0 = cv[2 * j]     - d0;
                float v1 = cv[2 * j + 1] - d1;
                if (v0 < best[r]) { best[r] = v0; bestk[r] = kbase + 32 * j; }
                if (v1 < best[r]) { best[r] = v1; bestk[r] = kbase + 32 * j + 1; }
            }
        }
    }

    // Cross-thread reduction: 16 tx-threads share each row. Reuse tile smem.
    __syncthreads();
    float* rv = smem;                    // [16][128]
    int*   ri = (int*)(smem + 2048);     // [16][128]
    int*   km = (int*)(smem + 4096);     // [128]
#pragma unroll
    for (int r = 0; r < 8; ++r) {
        rv[tx * BM + ty * 8 + r] = best[r];
        ri[tx * BM + ty * 8 + r] = bestk[r];
    }
    __syncthreads();
    if (t < BM) {
        float bv = rv[t];
        int   bk = ri[t];
#pragma unroll
        for (int i = 1; i < 16; ++i) {
            float v  = rv[i * BM + t];
            int   kk = ri[i * BM + t];
            if (v < bv || (v == bv && kk < bk)) { bv = v; bk = kk; }
        }
        km[t] = bk;
    }
    __syncthreads();

    // Gather winning codes: out[b, d, s0+r] = emb[d, km[r]].
    // Consecutive threads -> consecutive r -> fully coalesced stores.
    float* ob = out + (size_t)b * (DDIM * SPATIAL) + s0;
    for (int idx = t; idx < BM * DDIM; idx += NTHREADS) {
        const int r = idx & (BM - 1);
        const int d = idx >> 7;
        ob[d * SPATIAL + r] = __ldg(&emb[d * KCODES + km[r]]);
    }
}

// ---------------------------------------------------------------------------
extern "C" void kernel_launch(void* const* d_in, const int* in_sizes, int n_in,
                              void* d_out, int out_size) {
    const float* x   = (const float*)d_in[0];
    const float* emb = (const float*)d_in[1];
    // Defensive: x (8.4M elems) is larger than emb (0.5M elems).
    if (n_in >= 2 && in_sizes[0] < in_sizes[1]) {
        emb = (const float*)d_in[0];
        x   = (const float*)d_in[1];
    }
    float* out = (float*)d_out;

    cnorm_kernel<<<KCODES / 256, 256>>>(emb);
    nearest_main<<<(32 * SPATIAL) / BM, NTHREADS>>>(x, emb, out);
}